// round 15
// baseline (speedup 1.0000x reference)
#include <cuda_runtime.h>

#define NB      2
#define NPTS    8192
#define NDIM    64
#define KSEL    16
#define QB      32
#define CB      128
#define THREADS 256

// Precomputed squared norms (allocation-free scratch).
__device__ float g_sq[NB * NPTS];

// lexicographic (distance, index) ascending — stable top_k tie order
__device__ __forceinline__ bool keyless(float d1, int i1, float d2, int i2) {
    return (d1 < d2) || (d1 == d2 && i1 < i2);
}

// Serial insert into a shared sorted-16 list (lane 0 only). Re-checks the
// LIVE 16th entry, so stale screening thresholds are safe.
__device__ __forceinline__ void sins16(float* tl_d, int* tl_i, float dv, int idx) {
    if (keyless(dv, idx, tl_d[KSEL - 1], tl_i[KSEL - 1])) {
        int p = KSEL - 1;
        while (p > 0 && keyless(dv, idx, tl_d[p - 1], tl_i[p - 1])) {
            tl_d[p] = tl_d[p - 1];
            tl_i[p] = tl_i[p - 1];
            p--;
        }
        tl_d[p] = dv;
        tl_i[p] = idx;
    }
}

// ---------------------------------------------------------------------------
// Kernel 1: ||x||^2 per point — SAME sequential fma chain (c=0..63) as the
// dot products below, so the self-distance cancels to exactly 0 in fp32.
// ---------------------------------------------------------------------------
__global__ void norms_kernel(const float* __restrict__ x) {
    int p = blockIdx.x * blockDim.x + threadIdx.x;
    if (p >= NB * NPTS) return;
    int b = p >> 13;
    int n = p & (NPTS - 1);
    const float* xb = x + b * (NDIM * NPTS);
    float acc = 0.0f;
#pragma unroll
    for (int c = 0; c < NDIM; c++) {
        float v = xb[c * NPTS + n];
        acc = fmaf(v, v, acc);
    }
    g_sq[p] = acc;
}

// ---------------------------------------------------------------------------
// Kernel 2: fused Gram + warp-cooperative top-16.
//   Round-11 structure; (256,2) launch bounds grant ~128 regs (the 64-reg
//   4-block squeeze of rounds 10/11/14 de-pipelined the loop), and a 3-stage
//   rolling prefetch gives each LDS ~2 k-iterations (~64 cyc) of lead.
// ---------------------------------------------------------------------------
__global__ __launch_bounds__(THREADS, 2) void knn_kernel(const float* __restrict__ x,
                                                         float* __restrict__ out) {
    __shared__ __align__(16) float qs[NDIM * QB];   //  8 KB  [k][q]
    __shared__ __align__(16) float cs[NDIM * CB];   // 32 KB  [k][p]
    __shared__ float cssq[CB];
    __shared__ float qsq[QB];
    __shared__ float tld[QB * KSEL];
    __shared__ int   tli[QB * KSEL];

    const int tid    = threadIdx.x;
    const int b      = blockIdx.y;
    const int n_base = blockIdx.x * QB;
    const float* xb  = x + b * (NDIM * NPTS);
    const float* sqb = g_sq + b * NPTS;

    for (int i = tid; i < NDIM * QB; i += THREADS) {
        int q = i & (QB - 1);
        int k = i >> 5;
        qs[k * QB + q] = xb[k * NPTS + n_base + q];
    }
    if (tid < QB) qsq[tid] = sqb[n_base + tid];
    for (int i = tid; i < QB * KSEL; i += THREADS) {
        tld[i] = __int_as_float(0x7f800000);   // +inf
        tli[i] = 0x7fffffff;
    }
    __syncthreads();

    const int lane = tid & 31;
    const int warp = tid >> 5;
    const int qg   = tid >> 4;          // 0..15
    const int cg   = tid & 15;          // 0..15
    const float sq0 = qsq[2 * qg];
    const float sq1 = qsq[2 * qg + 1];

    const int myq0 = 4 * warp + 0 + ((lane >> 4) << 1);
    const int myq1 = 4 * warp + 1 + ((lane >> 4) << 1);

    const float2* qs2 = reinterpret_cast<const float2*>(qs);   // [k*16 + qg]
    const float4* csr = reinterpret_cast<const float4*>(cs);   // [k*32 + ...]
    float4*       csw = reinterpret_cast<float4*>(cs);
    const float4* x4  = reinterpret_cast<const float4*>(xb);

    for (int base = 0; base < NPTS; base += CB) {
        __syncthreads();   // previous tile fully consumed

        for (int i = tid; i < NDIM * (CB / 4); i += THREADS) {
            int p4 = i & 31;
            int c  = i >> 5;
            csw[c * (CB / 4) + p4] = x4[(c * NPTS + base) / 4 + p4];
        }
        if (tid < CB) cssq[tid] = sqb[base + tid];
        __syncthreads();

        // --- Gram micro-tile: 2 queries x 8 candidates, 3-stage rolling
        //     prefetch, fully unrolled (stage regs become registers). ---
        float a00 = 0.f, a01 = 0.f, a02 = 0.f, a03 = 0.f;
        float a04 = 0.f, a05 = 0.f, a06 = 0.f, a07 = 0.f;
        float a10 = 0.f, a11 = 0.f, a12 = 0.f, a13 = 0.f;
        float a14 = 0.f, a15 = 0.f, a16 = 0.f, a17 = 0.f;

        float2 sa[3];
        float4 sA[3], sB[3];
        sa[0] = qs2[qg];                 sa[1] = qs2[(QB / 2) + qg];
        sA[0] = csr[cg];                 sA[1] = csr[(CB / 4) + cg];
        sB[0] = csr[16 + cg];            sB[1] = csr[(CB / 4) + 16 + cg];

#pragma unroll
        for (int k = 0; k < NDIM; k++) {
            const int cur = k % 3;
            const int nxt = (k + 2) % 3;
            if (k + 2 < NDIM) {          // prefetch k+2: ~2 iterations of lead
                sa[nxt] = qs2[(k + 2) * (QB / 2) + qg];
                sA[nxt] = csr[(k + 2) * (CB / 4) + cg];
                sB[nxt] = csr[(k + 2) * (CB / 4) + 16 + cg];
            }
            const float2 a  = sa[cur];
            const float4 mA = sA[cur];
            const float4 mB = sB[cur];
            a00 = fmaf(a.x, mA.x, a00);
            a01 = fmaf(a.x, mA.y, a01);
            a02 = fmaf(a.x, mA.z, a02);
            a03 = fmaf(a.x, mA.w, a03);
            a04 = fmaf(a.x, mB.x, a04);
            a05 = fmaf(a.x, mB.y, a05);
            a06 = fmaf(a.x, mB.z, a06);
            a07 = fmaf(a.x, mB.w, a07);
            a10 = fmaf(a.y, mA.x, a10);
            a11 = fmaf(a.y, mA.y, a11);
            a12 = fmaf(a.y, mA.z, a12);
            a13 = fmaf(a.y, mA.w, a13);
            a14 = fmaf(a.y, mB.x, a14);
            a15 = fmaf(a.y, mB.y, a15);
            a16 = fmaf(a.y, mB.z, a16);
            a17 = fmaf(a.y, mB.w, a17);
        }

        // Distance epilogue (same expression/order as all passing rounds).
        float d0[8], d1[8];
        d0[0] = (sq0 + (-2.0f * a00));  d0[1] = (sq0 + (-2.0f * a01));
        d0[2] = (sq0 + (-2.0f * a02));  d0[3] = (sq0 + (-2.0f * a03));
        d0[4] = (sq0 + (-2.0f * a04));  d0[5] = (sq0 + (-2.0f * a05));
        d0[6] = (sq0 + (-2.0f * a06));  d0[7] = (sq0 + (-2.0f * a07));
        d1[0] = (sq1 + (-2.0f * a10));  d1[1] = (sq1 + (-2.0f * a11));
        d1[2] = (sq1 + (-2.0f * a12));  d1[3] = (sq1 + (-2.0f * a13));
        d1[4] = (sq1 + (-2.0f * a14));  d1[5] = (sq1 + (-2.0f * a15));
        d1[6] = (sq1 + (-2.0f * a16));  d1[7] = (sq1 + (-2.0f * a17));
#pragma unroll
        for (int j = 0; j < 8; j++) {
            int c = (j < 4) ? (4 * cg + j) : (64 + 4 * cg + (j - 4));
            float sc = cssq[c];
            d0[j] = d0[j] + sc;
            d1[j] = d1[j] + sc;
        }

        // --- Selection: one-shot screen per sub, slow path only if needed ---
#pragma unroll
        for (int sub = 0; sub < 2; sub++) {
            const int q_lo = 4 * warp + sub;
            const int q_hi = q_lo + 2;
            const int myq  = (sub == 0) ? myq0 : myq1;

            float thr  = tld[myq * KSEL + KSEL - 1];
            int   thri = tli[myq * KSEL + KSEL - 1];

            bool any = false;
#pragma unroll
            for (int j = 0; j < 8; j++) {
                float d = (sub == 0) ? d0[j] : d1[j];
                int   c = (j < 4) ? (4 * cg + j) : (64 + 4 * cg + (j - 4));
                any |= keyless(d, base + c, thr, thri);
            }

            unsigned scr = __ballot_sync(0xffffffffu, any);
            if (scr != 0u) {
#pragma unroll
                for (int j = 0; j < 8; j++) {
                    float d   = (sub == 0) ? d0[j] : d1[j];
                    int   cme = (j < 4) ? (4 * cg + j) : (64 + 4 * cg + (j - 4));
                    float lt  = tld[myq * KSEL + KSEL - 1];
                    int   lti = tli[myq * KSEL + KSEL - 1];
                    bool pass = keyless(d, base + cme, lt, lti);
                    unsigned bal = __ballot_sync(0xffffffffu, pass);
                    if (bal) {
                        unsigned lom = bal & 0xffffu;
                        while (lom) {
                            int src = __ffs(lom) - 1;
                            lom &= lom - 1;
                            float dv = __shfl_sync(0xffffffffu, d, src);
                            if (lane == 0) {
                                int c = (j < 4) ? (4 * src + j) : (64 + 4 * src + (j - 4));
                                sins16(tld + q_lo * KSEL, tli + q_lo * KSEL, dv, base + c);
                            }
                        }
                        unsigned him = bal >> 16;
                        while (him) {
                            int s = __ffs(him) - 1;
                            him &= him - 1;
                            float dv = __shfl_sync(0xffffffffu, d, s + 16);
                            if (lane == 0) {
                                int c = (j < 4) ? (4 * s + j) : (64 + 4 * s + (j - 4));
                                sins16(tld + q_hi * KSEL, tli + q_hi * KSEL, dv, base + c);
                            }
                        }
                        __syncwarp();
                    }
                }
            }
        }
    }

    // Output (2, NB, NPTS, KSEL), float32 values.
    __syncthreads();
    for (int i = tid; i < QB * KSEL; i += THREADS) {
        int q = i >> 4;
        int k = i & (KSEL - 1);
        int n = n_base + q;
        int base0 = (b * NPTS + n) * KSEL + k;            // plane 0: nn_idx
        int base1 = NB * NPTS * KSEL + base0;             // plane 1: center_idx
        out[base0] = (float)tli[q * KSEL + k];
        out[base1] = (float)n;
    }
}

extern "C" void kernel_launch(void* const* d_in, const int* in_sizes, int n_in,
                              void* d_out, int out_size) {
    const float* x = (const float*)d_in[0];
    float* out = (float*)d_out;
    norms_kernel<<<(NB * NPTS + 255) / 256, 256>>>(x);
    knn_kernel<<<dim3(NPTS / QB, NB), THREADS>>>(x, out);
}

// round 16
// speedup vs baseline: 2.1100x; 2.1100x over previous
#include <cuda_runtime.h>

#define NB      2
#define NPTS    8192
#define NDIM    64
#define KSEL    16
#define NSPLIT  4
#define CPT     (NPTS / NSPLIT)   // 2048 candidates per thread

// Scratch (allocation-free rule: __device__ globals).
__device__ float g_sq[NB * NPTS];
__device__ float g_pd[NB * NPTS * NSPLIT * KSEL];   // partial top-16 dists
__device__ int   g_pi[NB * NPTS * NSPLIT * KSEL];   // partial top-16 indices

// lexicographic (distance, index) ascending — stable top_k tie order
__device__ __forceinline__ bool keyless(float d1, int i1, float d2, int i2) {
    return (d1 < d2) || (d1 == d2 && i1 < i2);
}

// Branch-free insert into register-resident sorted-16 list (round-8 verified).
__device__ __forceinline__ void ins16(float (&ld)[KSEL], int (&li)[KSEL],
                                      float dv, int idx) {
    int rank = 0;
#pragma unroll
    for (int p = 0; p < KSEL; p++)
        rank += keyless(ld[p], li[p], dv, idx) ? 1 : 0;
#pragma unroll
    for (int p = KSEL - 1; p > 0; p--) {
        bool here  = (p == rank);
        bool shift = (p > rank);
        ld[p] = here ? dv  : (shift ? ld[p - 1] : ld[p]);
        li[p] = here ? idx : (shift ? li[p - 1] : li[p]);
    }
    if (rank == 0) { ld[0] = dv; li[0] = idx; }
}

// ---------------------------------------------------------------------------
// Kernel 1: ||x||^2 per point, sequential fma chain c=0..63 (matches the dot
// chains below, so self-distance cancels to exactly 0 in fp32).
// ---------------------------------------------------------------------------
__global__ void norms_kernel(const float* __restrict__ x) {
    int p = blockIdx.x * blockDim.x + threadIdx.x;
    if (p >= NB * NPTS) return;
    int b = p >> 13;
    int n = p & (NPTS - 1);
    const float* xb = x + b * (NDIM * NPTS);
    float acc = 0.0f;
#pragma unroll
    for (int c = 0; c < NDIM; c++) {
        float v = xb[c * NPTS + n];
        acc = fmaf(v, v, acc);
    }
    g_sq[p] = acc;
}

// ---------------------------------------------------------------------------
// Kernel 2: split brute-force KNN — round 8's proven-fast loop shape
// (register query, warp-uniform candidate LDG, register top-16) scaled to
// full occupancy via a 4-way candidate split, with precomputed norms and
// m-vectorized uniform LDG.128 (one load feeds 4 candidates).
//   global warp gw: split = gw & 3, query-warp = gw >> 2;
//   thread's query = 32*(gw>>2) + lane  (lane-varying -> q loads coalesced;
//   candidate loads warp-uniform -> L1 broadcast, MLP ~64).
// ---------------------------------------------------------------------------
__global__ __launch_bounds__(128, 4) void knn_split(const float* __restrict__ x) {
    const int gw   = (blockIdx.x * 128 + threadIdx.x) >> 5;   // 0..2047
    const int lane = threadIdx.x & 31;
    const int split = gw & (NSPLIT - 1);
    const int gq    = (gw >> 2) * 32 + lane;                  // 0..16383
    const int b     = gq >> 13;
    const int n     = gq & (NPTS - 1);
    const float* xb = x + b * (NDIM * NPTS);
    const float* sqb = g_sq + b * NPTS;

    // Query vector in registers (coalesced loads across lanes).
    float q[NDIM];
#pragma unroll
    for (int c = 0; c < NDIM; c++)
        q[c] = xb[c * NPTS + n];
    const float sqn = sqb[n];

    float ld[KSEL];
    int   li[KSEL];
#pragma unroll
    for (int p = 0; p < KSEL; p++) {
        ld[p] = __int_as_float(0x7f800000);   // +inf
        li[p] = 0x7fffffff;
    }

    const int m0 = split * CPT;
    for (int m = m0; m < m0 + CPT; m += 4) {
        float d0 = 0.f, d1 = 0.f, d2 = 0.f, d3 = 0.f;
#pragma unroll
        for (int c = 0; c < NDIM; c++) {
            // Warp-uniform LDG.128: candidates m..m+3, dim c.
            float4 v = *reinterpret_cast<const float4*>(xb + c * NPTS + m);
            d0 = fmaf(q[c], v.x, d0);
            d1 = fmaf(q[c], v.y, d1);
            d2 = fmaf(q[c], v.z, d2);
            d3 = fmaf(q[c], v.w, d3);
        }
        float4 sm = *reinterpret_cast<const float4*>(sqb + m);  // uniform
        d0 = (sqn + (-2.0f * d0)) + sm.x;
        d1 = (sqn + (-2.0f * d1)) + sm.y;
        d2 = (sqn + (-2.0f * d2)) + sm.z;
        d3 = (sqn + (-2.0f * d3)) + sm.w;

        // Sequential m order -> stable lexicographic selection (== top_k).
        if (d0 < ld[KSEL-1] || (d0 == ld[KSEL-1] && (m+0) < li[KSEL-1])) ins16(ld, li, d0, m+0);
        if (d1 < ld[KSEL-1] || (d1 == ld[KSEL-1] && (m+1) < li[KSEL-1])) ins16(ld, li, d1, m+1);
        if (d2 < ld[KSEL-1] || (d2 == ld[KSEL-1] && (m+2) < li[KSEL-1])) ins16(ld, li, d2, m+2);
        if (d3 < ld[KSEL-1] || (d3 == ld[KSEL-1] && (m+3) < li[KSEL-1])) ins16(ld, li, d3, m+3);
    }

    // Write this split's sorted partial list.
    const int base = (gq * NSPLIT + split) * KSEL;
#pragma unroll
    for (int e = 0; e < KSEL; e++) {
        g_pd[base + e] = ld[e];
        g_pi[base + e] = li[e];
    }
}

// ---------------------------------------------------------------------------
// Kernel 3: exact 4-way merge of sorted partial lists + output.
// ---------------------------------------------------------------------------
__global__ void merge_kernel(float* __restrict__ out) {
    int gq = blockIdx.x * blockDim.x + threadIdx.x;
    if (gq >= NB * NPTS) return;
    int n = gq & (NPTS - 1);

    int head[NSPLIT];
    int lbase[NSPLIT];
#pragma unroll
    for (int s = 0; s < NSPLIT; s++) {
        head[s]  = 0;
        lbase[s] = (gq * NSPLIT + s) * KSEL;
    }

    int out0 = gq * KSEL;                       // plane 0: nn_idx
    int out1 = NB * NPTS * KSEL + out0;         // plane 1: center_idx
#pragma unroll
    for (int k = 0; k < KSEL; k++) {
        float bd = __int_as_float(0x7f800000);
        int   bi = 0x7fffffff;
        int   bs = 0;
        bool  first = true;
#pragma unroll
        for (int s = 0; s < NSPLIT; s++) {
            if (head[s] < KSEL) {
                float d = g_pd[lbase[s] + head[s]];
                int   i = g_pi[lbase[s] + head[s]];
                if (first || keyless(d, i, bd, bi)) { bd = d; bi = i; bs = s; first = false; }
            }
        }
        head[bs]++;
        out[out0 + k] = (float)bi;
        out[out1 + k] = (float)n;
    }
}

// ---------------------------------------------------------------------------
extern "C" void kernel_launch(void* const* d_in, const int* in_sizes, int n_in,
                              void* d_out, int out_size) {
    const float* x = (const float*)d_in[0];
    float* out = (float*)d_out;
    norms_kernel<<<(NB * NPTS + 255) / 256, 256>>>(x);
    knn_split<<<(NB * NPTS * NSPLIT) / 128, 128>>>(x);
    merge_kernel<<<(NB * NPTS + 127) / 128, 128>>>(out);
}